// round 16
// baseline (speedup 1.0000x reference)
#include <cuda_runtime.h>
#include <cuda_bf16.h>

// GaussianRender, single fused launch: 256 CTAs = 64 tiles x 4 quarters
// (16 rows = 4 bands of 4 rows), 256 threads, 4 px/thread.
// alpha = clip(op*prob,.01,.99): band-far gaussians (per-axis Schur bound)
// contribute exactly alpha=0.01; runs of far gaussians collapse to
//   acc += T0*(q*S1) - q^2*S2rel,  T -= q*m   (pixel-independent sums).
// Render walks the band near-bitmap directly; gap sums from q-prescaled,
// lane-duplicated prefix sums (E2 stored NEGATED so the S2 term lands with
// the correct minus sign); near params from pre-duplicated rec2.
// No emit phase, no atomics, 2 barriers, exact for ANY near count.

#define KG     256
#define WIMG   512
#define NB     4             // bands per CTA (4 rows each)

typedef unsigned long long u64;
union F2U { float2 f; u64 u; };

__device__ __forceinline__ u64 pk(float a, float b) { F2U t; t.f = make_float2(a, b); return t.u; }
__device__ __forceinline__ u64 ffma2(u64 a, u64 b, u64 c) {
    u64 d; asm("fma.rn.f32x2 %0, %1, %2, %3;" : "=l"(d) : "l"(a), "l"(b), "l"(c)); return d;
}
__device__ __forceinline__ u64 fmul2(u64 a, u64 b) {
    u64 d; asm("mul.rn.f32x2 %0, %1, %2;" : "=l"(d) : "l"(a), "l"(b)); return d;
}
__device__ __forceinline__ u64 fadd2(u64 a, u64 b) {
    u64 d; asm("add.rn.f32x2 %0, %1, %2;" : "=l"(d) : "l"(a), "l"(b)); return d;
}
__device__ __forceinline__ float ex2f(float x) {
    float y; asm("ex2.approx.f32 %0, %1;" : "=f"(y) : "f"(x)); return y;
}
__device__ __forceinline__ float lg2f(float x) {
    float y; asm("lg2.approx.f32 %0, %1;" : "=f"(y) : "f"(x)); return y;
}
__device__ __forceinline__ float clampa(float a) { return fminf(fmaxf(a, 0.01f), 0.99f); }

#define T_FAR (-6.6438561897747395f - 0.01f)   // log2(0.01) - margin

__global__ __launch_bounds__(256)
void fused_kernel(const float* __restrict__ mu,
                  const float* __restrict__ cov,
                  const float* __restrict__ opac,
                  const float* __restrict__ col,
                  const int*   __restrict__ tidx,
                  float*       __restrict__ out)
{
    // rec2[j]: 0=-mx 1=-my 2=k1 3=k2 4=k3 5=lop 6=cr 7=cg 8=cb  (lane-dup u64)
    __shared__ u64 rec2[KG][9];                 // 18 KB
    __shared__ u64 E1[3][KG + 1];               //  q   * prefix(c)   , 6.2 KB
    __shared__ u64 E2[3][KG + 1];               // -q^2 * prefix(j*c) , 6.2 KB
    __shared__ float wsum[6][8];
    __shared__ unsigned int bandmask[NB][8];    // depth-ordered near bitmaps

    const int bid  = blockIdx.x;
    const int t    = bid >> 2;       // tile 0..63
    const int qtr  = bid & 3;        // quarter: rows qtr*16 .. +15
    const int tx   = t & 7;
    const int ty   = t >> 3;
    const int tid  = threadIdx.x;    // 0..255 = depth slot j
    const int lane = tid & 31;
    const int warp = tid >> 5;

    const float x0 = (float)(tx * 64) + 0.5f, x1 = x0 + 63.0f;
    const float ybase = (float)(ty * 64 + qtr * 16) + 0.5f;

    // ---- phase 1: gather + params + band ballots + warp scans ----
    float vv[6], inc[6];
    {
        const int g = __ldg(tidx + t * KG + tid);
        const float4 cv = __ldg((const float4*)(cov + g * 4));
        const float2 m  = __ldg((const float2*)(mu + g * 2));
        const float op  = __ldg(opac + g);
        const float cr  = __ldg(col + g * 3 + 0);
        const float cg  = __ldg(col + g * 3 + 1);
        const float cb  = __ldg(col + g * 3 + 2);

        const float det = fmaxf(fmaf(cv.x, cv.w, -cv.y * cv.z), 1e-6f);
        const float inv = 1.0f / det;
        const float e  = -0.7213475204444817f;   // -0.5 * log2(e)
        const float k1 = e * cv.w * inv;
        const float k2 = -e * (cv.y + cv.z) * inv;
        const float k3 = e * cv.x * inv;
        const float lop = lg2f(op);

        rec2[tid][0] = pk(-m.x, -m.x);
        rec2[tid][1] = pk(-m.y, -m.y);
        rec2[tid][2] = pk(k1, k1);
        rec2[tid][3] = pk(k2, k2);
        rec2[tid][4] = pk(k3, k3);
        rec2[tid][5] = pk(lop, lop);
        rec2[tid][6] = pk(cr, cr);
        rec2[tid][7] = pk(cg, cg);
        rec2[tid][8] = pk(cb, cb);

        // per-axis Schur bound; ballots preserve depth order (warp = 32 slots)
        const float dlo = x0 - m.x, dhi = x1 - m.x;
        const float mdx = fmaxf(fmaxf(dlo, -dhi), 0.0f);
        const float bxp = __fdividef(e * mdx * mdx, cv.x) + lop;
        const bool xnear = (bxp >= T_FAR);
        #pragma unroll
        for (int b = 0; b < NB; ++b) {
            const float yb0 = ybase + (float)(b * 4);
            const float yb1 = yb0 + 3.0f;
            const float elo = yb0 - m.y, ehi = yb1 - m.y;
            const float mdy = fmaxf(fmaxf(elo, -ehi), 0.0f);
            const float byp = __fdividef(e * mdy * mdy, cv.w) + lop;
            const bool nb = xnear && (byp >= T_FAR);
            const unsigned int mk = __ballot_sync(0xffffffffu, nb);
            if (lane == 0) bandmask[b][warp] = mk;
        }

        // inclusive warp scans of (c, j*c)
        const float fj = (float)tid;
        vv[0] = cr; vv[1] = cg; vv[2] = cb;
        vv[3] = fj * cr; vv[4] = fj * cg; vv[5] = fj * cb;
        #pragma unroll
        for (int q = 0; q < 6; ++q) {
            float x = vv[q];
            #pragma unroll
            for (int o = 1; o < 32; o <<= 1) {
                const float n = __shfl_up_sync(0xffffffffu, x, o);
                if (lane >= o) x += n;
            }
            inc[q] = x;
            if (lane == 31) wsum[q][warp] = x;
        }
    }
    __syncthreads();

    // ---- phase 2: finalize exclusive prefix sums (E2 NEGATED) ----
    {
        float off[6] = {0.f, 0.f, 0.f, 0.f, 0.f, 0.f};
        #pragma unroll
        for (int w = 0; w < 8; ++w) {
            if (w < warp) {
                #pragma unroll
                for (int q = 0; q < 6; ++q) off[q] += wsum[q][w];
            }
        }
        const float Q = 0.01f, NQ2 = -1e-4f;
        #pragma unroll
        for (int c = 0; c < 3; ++c) {
            const float e1 = Q   * (off[c]     + inc[c]     - vv[c]);
            const float e2 = NQ2 * (off[c + 3] + inc[c + 3] - vv[c + 3]);
            E1[c][tid] = pk(e1, e1);
            E2[c][tid] = pk(e2, e2);
        }
        if (tid == KG - 1) {
            #pragma unroll
            for (int c = 0; c < 3; ++c) {
                const float e1 = Q   * (off[c]     + inc[c]);
                const float e2 = NQ2 * (off[c + 3] + inc[c + 3]);
                E1[c][KG] = pk(e1, e1);
                E2[c][KG] = pk(e2, e2);
            }
        }
    }
    __syncthreads();

    // ---- phase 3: render 4 px/thread straight from bitmap + E + rec2 ----
    const int lx = tid & 63;
    const int bl = tid >> 6;                     // band 0..3 (warp-uniform)
    const float px  = (float)(tx * 64 + lx) + 0.5f;
    const float py0 = ybase + (float)(bl * 4);
    const u64 px2 = pk(px, px);
    const u64 pyA = pk(py0, py0 + 1.0f);
    const u64 pyB = pk(py0 + 2.0f, py0 + 3.0f);
    const u64 m1  = pk(-1.0f, -1.0f);

    u64 aR0 = 0, aG0 = 0, aB0 = 0, aR1 = 0, aG1 = 0, aB1 = 0;
    u64 trA = pk(1.0f, 1.0f), trB = pk(1.0f, 1.0f);

    // gap [s,e): diffs give qS1 = q*sum(c), D2 = -q^2*sum(j*c);
    // S2term = D2 + (q*s)*(qS1) = -q^2*sum((j-s)*c). acc += tr*qS1 + S2term.
    #define GAP(s, e)                                                        \
    {                                                                        \
        u64 S1r = ffma2(E1[0][s], m1, E1[0][e]);                             \
        u64 S1g = ffma2(E1[1][s], m1, E1[1][e]);                             \
        u64 S1b = ffma2(E1[2][s], m1, E1[2][e]);                             \
        u64 S2r = ffma2(E2[0][s], m1, E2[0][e]);                             \
        u64 S2g = ffma2(E2[1][s], m1, E2[1][e]);                             \
        u64 S2b = ffma2(E2[2][s], m1, E2[2][e]);                             \
        const float fqs = 0.01f * (float)(s);                                \
        const u64 pfqs = pk(fqs, fqs);                                       \
        S2r = ffma2(S1r, pfqs, S2r);                                         \
        S2g = ffma2(S1g, pfqs, S2g);                                         \
        S2b = ffma2(S1b, pfqs, S2b);                                         \
        aR0 = ffma2(trA, S1r, aR0);  aR0 = fadd2(aR0, S2r);                  \
        aG0 = ffma2(trA, S1g, aG0);  aG0 = fadd2(aG0, S2g);                  \
        aB0 = ffma2(trA, S1b, aB0);  aB0 = fadd2(aB0, S2b);                  \
        aR1 = ffma2(trB, S1r, aR1);  aR1 = fadd2(aR1, S2r);                  \
        aG1 = ffma2(trB, S1g, aG1);  aG1 = fadd2(aG1, S2g);                  \
        aB1 = ffma2(trB, S1b, aB1);  aB1 = fadd2(aB1, S2b);                  \
        const float qm = 0.01f * (float)((e) - (s));                         \
        const u64 nqm = pk(-qm, -qm);                                        \
        trA = fadd2(trA, nqm);                                               \
        trB = fadd2(trB, nqm);                                               \
    }

    int last = 0;
    #pragma unroll 1
    for (int w = 0; w < 8; ++w) {
        unsigned int mm = bandmask[bl][w];
        while (mm) {
            const int j = w * 32 + __ffs(mm) - 1;
            mm &= mm - 1;
            GAP(last, j)
            // near gaussian j
            {
                const u64 nmx = rec2[j][0], nmy = rec2[j][1];
                const u64 k1d = rec2[j][2], k2d = rec2[j][3], k3d = rec2[j][4];
                const u64 lop = rec2[j][5];
                const u64 crr = rec2[j][6], cgg = rec2[j][7], cbb = rec2[j][8];
                const u64 dx2 = fadd2(px2, nmx);
                const u64 t0  = fmul2(k1d, dx2);
                const u64 u2  = ffma2(t0, dx2, lop);
                const u64 kx2 = fmul2(k2d, dx2);
                const u64 dyA = fadd2(pyA, nmy);
                const u64 qA  = ffma2(k3d, dyA, kx2);
                const u64 pwA = ffma2(dyA, qA, u2);
                const u64 dyB = fadd2(pyB, nmy);
                const u64 qB  = ffma2(k3d, dyB, kx2);
                const u64 pwB = ffma2(dyB, qB, u2);
                F2U PA, PB; PA.u = pwA; PB.u = pwB;
                F2U alA, alB;
                alA.f.x = clampa(ex2f(PA.f.x));
                alA.f.y = clampa(ex2f(PA.f.y));
                alB.f.x = clampa(ex2f(PB.f.x));
                alB.f.y = clampa(ex2f(PB.f.y));
                const u64 wvA = fmul2(alA.u, trA);
                trA = ffma2(alA.u, m1, trA);
                const u64 wvB = fmul2(alB.u, trB);
                trB = ffma2(alB.u, m1, trB);
                aR0 = ffma2(wvA, crr, aR0);
                aG0 = ffma2(wvA, cgg, aG0);
                aB0 = ffma2(wvA, cbb, aB0);
                aR1 = ffma2(wvB, crr, aR1);
                aG1 = ffma2(wvB, cgg, aG1);
                aB1 = ffma2(wvB, cbb, aB1);
            }
            last = j + 1;
        }
    }
    GAP(last, KG)
    #undef GAP

    // ---- epilogue: write 4 pixels ----
    const int gx = tx * 64 + lx;
    const int gy = ty * 64 + qtr * 16 + bl * 4;
    F2U R0, G0, B0, R1, G1, B1;
    R0.u = aR0; G0.u = aG0; B0.u = aB0;
    R1.u = aR1; G1.u = aG1; B1.u = aB1;
    float* o = out + ((size_t)gy * WIMG + gx) * 3;
    o[0] = R0.f.x; o[1] = G0.f.x; o[2] = B0.f.x;  o += WIMG * 3;
    o[0] = R0.f.y; o[1] = G0.f.y; o[2] = B0.f.y;  o += WIMG * 3;
    o[0] = R1.f.x; o[1] = G1.f.x; o[2] = B1.f.x;  o += WIMG * 3;
    o[0] = R1.f.y; o[1] = G1.f.y; o[2] = B1.f.y;
}

extern "C" void kernel_launch(void* const* d_in, const int* in_sizes, int n_in,
                              void* d_out, int out_size)
{
    const float* mu   = (const float*)d_in[0];
    const float* cov  = (const float*)d_in[1];
    const float* opac = (const float*)d_in[2];
    const float* col  = (const float*)d_in[3];
    const int*   tidx = (const int*)  d_in[4];
    float* out = (float*)d_out;

    // 64 tiles x 4 quarters = 256 CTAs, 256 threads, single launch
    fused_kernel<<<256, 256>>>(mu, cov, opac, col, tidx, out);
}

// round 17
// speedup vs baseline: 1.0208x; 1.0208x over previous
#include <cuda_runtime.h>
#include <cuda_bf16.h>

// GaussianRender, single fused launch: 256 CTAs = 64 tiles x 4 quarters
// (16 rows = 4 bands of 4 rows), 256 threads, 4 px/thread.
// alpha = clip(op*prob,.01,.99): band-far gaussians (per-axis Schur bound)
// contribute exactly alpha=0.01; runs of far gaussians collapse to
//   acc += T0*(q*S1) - q^2*S2rel,  T -= q*m   (pixel-independent sums).
// R17: all smem render data paired into ulonglong2 (each half lane-dup) so
// the mainloop uses LDS.128 -> ~2x fewer L1tex wavefronts than R16.
// Render walks the band near-bitmap directly; no emit phase, no atomics,
// 2 barriers, exact for ANY near count.

#define KG     256
#define WIMG   512
#define NB     4             // bands per CTA (4 rows each)

typedef unsigned long long u64;
union F2U { float2 f; u64 u; };

__device__ __forceinline__ u64 pk(float a, float b) { F2U t; t.f = make_float2(a, b); return t.u; }
__device__ __forceinline__ u64 ffma2(u64 a, u64 b, u64 c) {
    u64 d; asm("fma.rn.f32x2 %0, %1, %2, %3;" : "=l"(d) : "l"(a), "l"(b), "l"(c)); return d;
}
__device__ __forceinline__ u64 fmul2(u64 a, u64 b) {
    u64 d; asm("mul.rn.f32x2 %0, %1, %2;" : "=l"(d) : "l"(a), "l"(b)); return d;
}
__device__ __forceinline__ u64 fadd2(u64 a, u64 b) {
    u64 d; asm("add.rn.f32x2 %0, %1, %2;" : "=l"(d) : "l"(a), "l"(b)); return d;
}
__device__ __forceinline__ float ex2f(float x) {
    float y; asm("ex2.approx.f32 %0, %1;" : "=f"(y) : "f"(x)); return y;
}
__device__ __forceinline__ float lg2f(float x) {
    float y; asm("lg2.approx.f32 %0, %1;" : "=f"(y) : "f"(x)); return y;
}
__device__ __forceinline__ float clampa(float a) { return fminf(fmaxf(a, 0.01f), 0.99f); }

#define T_FAR (-6.6438561897747395f - 0.01f)   // log2(0.01) - margin

__global__ __launch_bounds__(256)
void fused_kernel(const float* __restrict__ mu,
                  const float* __restrict__ cov,
                  const float* __restrict__ opac,
                  const float* __restrict__ col,
                  const int*   __restrict__ tidx,
                  float*       __restrict__ out)
{
    // rec2[j]: {nmx,nmy} {k1,k2} {k3,lop} {cr,cg} {cb,cb} — each u64 lane-dup
    __shared__ __align__(16) ulonglong2 rec2[KG][5];     // 20 KB
    // EP[0]={qE1r,qE1g} EP[1]={qE1b,-q^2E2r} EP[2]={-q^2E2g,-q^2E2b}
    __shared__ __align__(16) ulonglong2 EP[3][KG + 1];   // 12.3 KB
    __shared__ float wsum[6][8];
    __shared__ unsigned int bandmask[NB][8];    // depth-ordered near bitmaps

    const int bid  = blockIdx.x;
    const int t    = bid >> 2;       // tile 0..63
    const int qtr  = bid & 3;        // quarter: rows qtr*16 .. +15
    const int tx   = t & 7;
    const int ty   = t >> 3;
    const int tid  = threadIdx.x;    // 0..255 = depth slot j
    const int lane = tid & 31;
    const int warp = tid >> 5;

    const float x0 = (float)(tx * 64) + 0.5f, x1 = x0 + 63.0f;
    const float ybase = (float)(ty * 64 + qtr * 16) + 0.5f;

    // ---- phase 1: gather + params + band ballots + warp scans ----
    float vv[6], inc[6];
    {
        const int g = __ldg(tidx + t * KG + tid);
        const float4 cv = __ldg((const float4*)(cov + g * 4));
        const float2 m  = __ldg((const float2*)(mu + g * 2));
        const float op  = __ldg(opac + g);
        const float cr  = __ldg(col + g * 3 + 0);
        const float cg  = __ldg(col + g * 3 + 1);
        const float cb  = __ldg(col + g * 3 + 2);

        const float det = fmaxf(fmaf(cv.x, cv.w, -cv.y * cv.z), 1e-6f);
        const float inv = 1.0f / det;
        const float e  = -0.7213475204444817f;   // -0.5 * log2(e)
        const float k1 = e * cv.w * inv;
        const float k2 = -e * (cv.y + cv.z) * inv;
        const float k3 = e * cv.x * inv;
        const float lop = lg2f(op);

        rec2[tid][0] = make_ulonglong2(pk(-m.x, -m.x), pk(-m.y, -m.y));
        rec2[tid][1] = make_ulonglong2(pk(k1, k1),     pk(k2, k2));
        rec2[tid][2] = make_ulonglong2(pk(k3, k3),     pk(lop, lop));
        rec2[tid][3] = make_ulonglong2(pk(cr, cr),     pk(cg, cg));
        rec2[tid][4] = make_ulonglong2(pk(cb, cb),     pk(cb, cb));

        // per-axis Schur bound; ballots preserve depth order (warp = 32 slots)
        const float dlo = x0 - m.x, dhi = x1 - m.x;
        const float mdx = fmaxf(fmaxf(dlo, -dhi), 0.0f);
        const float bxp = __fdividef(e * mdx * mdx, cv.x) + lop;
        const bool xnear = (bxp >= T_FAR);
        #pragma unroll
        for (int b = 0; b < NB; ++b) {
            const float yb0 = ybase + (float)(b * 4);
            const float yb1 = yb0 + 3.0f;
            const float elo = yb0 - m.y, ehi = yb1 - m.y;
            const float mdy = fmaxf(fmaxf(elo, -ehi), 0.0f);
            const float byp = __fdividef(e * mdy * mdy, cv.w) + lop;
            const bool nb = xnear && (byp >= T_FAR);
            const unsigned int mk = __ballot_sync(0xffffffffu, nb);
            if (lane == 0) bandmask[b][warp] = mk;
        }

        // inclusive warp scans of (c, j*c)
        const float fj = (float)tid;
        vv[0] = cr; vv[1] = cg; vv[2] = cb;
        vv[3] = fj * cr; vv[4] = fj * cg; vv[5] = fj * cb;
        #pragma unroll
        for (int q = 0; q < 6; ++q) {
            float x = vv[q];
            #pragma unroll
            for (int o = 1; o < 32; o <<= 1) {
                const float n = __shfl_up_sync(0xffffffffu, x, o);
                if (lane >= o) x += n;
            }
            inc[q] = x;
            if (lane == 31) wsum[q][warp] = x;
        }
    }
    __syncthreads();

    // ---- phase 2: finalize exclusive prefix sums (E2 NEGATED), paired ----
    {
        float off[6] = {0.f, 0.f, 0.f, 0.f, 0.f, 0.f};
        #pragma unroll
        for (int w = 0; w < 8; ++w) {
            if (w < warp) {
                #pragma unroll
                for (int q = 0; q < 6; ++q) off[q] += wsum[q][w];
            }
        }
        const float Q = 0.01f, NQ2 = -1e-4f;
        const float e1r = Q   * (off[0] + inc[0] - vv[0]);
        const float e1g = Q   * (off[1] + inc[1] - vv[1]);
        const float e1b = Q   * (off[2] + inc[2] - vv[2]);
        const float n2r = NQ2 * (off[3] + inc[3] - vv[3]);
        const float n2g = NQ2 * (off[4] + inc[4] - vv[4]);
        const float n2b = NQ2 * (off[5] + inc[5] - vv[5]);
        EP[0][tid] = make_ulonglong2(pk(e1r, e1r), pk(e1g, e1g));
        EP[1][tid] = make_ulonglong2(pk(e1b, e1b), pk(n2r, n2r));
        EP[2][tid] = make_ulonglong2(pk(n2g, n2g), pk(n2b, n2b));
        if (tid == KG - 1) {
            const float f1r = Q   * (off[0] + inc[0]);
            const float f1g = Q   * (off[1] + inc[1]);
            const float f1b = Q   * (off[2] + inc[2]);
            const float m2r = NQ2 * (off[3] + inc[3]);
            const float m2g = NQ2 * (off[4] + inc[4]);
            const float m2b = NQ2 * (off[5] + inc[5]);
            EP[0][KG] = make_ulonglong2(pk(f1r, f1r), pk(f1g, f1g));
            EP[1][KG] = make_ulonglong2(pk(f1b, f1b), pk(m2r, m2r));
            EP[2][KG] = make_ulonglong2(pk(m2g, m2g), pk(m2b, m2b));
        }
    }
    __syncthreads();

    // ---- phase 3: render 4 px/thread straight from bitmap + EP + rec2 ----
    const int lx = tid & 63;
    const int bl = tid >> 6;                     // band 0..3 (warp-uniform)
    const float px  = (float)(tx * 64 + lx) + 0.5f;
    const float py0 = ybase + (float)(bl * 4);
    const u64 px2 = pk(px, px);
    const u64 pyA = pk(py0, py0 + 1.0f);
    const u64 pyB = pk(py0 + 2.0f, py0 + 3.0f);
    const u64 m1  = pk(-1.0f, -1.0f);

    u64 aR0 = 0, aG0 = 0, aB0 = 0, aR1 = 0, aG1 = 0, aB1 = 0;
    u64 trA = pk(1.0f, 1.0f), trB = pk(1.0f, 1.0f);

    // gap [s,e): qS1 = q*sum(c), D2 = -q^2*sum(j*c);
    // S2term = D2 + (q*s)*qS1 = -q^2*sum((j-s)*c). acc += tr*qS1 + S2term.
    // (s,e warp-uniform -> uniform branch)
    #define GAP(s, e)                                                        \
    if ((e) > (s)) {                                                         \
        const ulonglong2 As = EP[0][s], Bs = EP[1][s], Cs = EP[2][s];        \
        const ulonglong2 Ae = EP[0][e], Be = EP[1][e], Ce = EP[2][e];        \
        const u64 S1r = ffma2(As.x, m1, Ae.x);                               \
        const u64 S1g = ffma2(As.y, m1, Ae.y);                               \
        const u64 S1b = ffma2(Bs.x, m1, Be.x);                               \
        u64 S2r = ffma2(Bs.y, m1, Be.y);                                     \
        u64 S2g = ffma2(Cs.x, m1, Ce.x);                                     \
        u64 S2b = ffma2(Cs.y, m1, Ce.y);                                     \
        const float fqs = 0.01f * (float)(s);                                \
        const u64 pfqs = pk(fqs, fqs);                                       \
        S2r = ffma2(S1r, pfqs, S2r);                                         \
        S2g = ffma2(S1g, pfqs, S2g);                                         \
        S2b = ffma2(S1b, pfqs, S2b);                                         \
        aR0 = ffma2(trA, S1r, aR0);  aR0 = fadd2(aR0, S2r);                  \
        aG0 = ffma2(trA, S1g, aG0);  aG0 = fadd2(aG0, S2g);                  \
        aB0 = ffma2(trA, S1b, aB0);  aB0 = fadd2(aB0, S2b);                  \
        aR1 = ffma2(trB, S1r, aR1);  aR1 = fadd2(aR1, S2r);                  \
        aG1 = ffma2(trB, S1g, aG1);  aG1 = fadd2(aG1, S2g);                  \
        aB1 = ffma2(trB, S1b, aB1);  aB1 = fadd2(aB1, S2b);                  \
        const float qm = 0.01f * (float)((e) - (s));                         \
        const u64 nqm = pk(-qm, -qm);                                        \
        trA = fadd2(trA, nqm);                                               \
        trB = fadd2(trB, nqm);                                               \
    }

    int last = 0;
    #pragma unroll 1
    for (int w = 0; w < 8; ++w) {
        unsigned int mm = bandmask[bl][w];
        while (mm) {
            const int j = w * 32 + __ffs(mm) - 1;
            mm &= mm - 1;
            GAP(last, j)
            // near gaussian j (5 x LDS.128)
            {
                const ulonglong2 r0 = rec2[j][0];   // nmx, nmy
                const ulonglong2 r1 = rec2[j][1];   // k1, k2
                const ulonglong2 r2 = rec2[j][2];   // k3, lop
                const ulonglong2 r3 = rec2[j][3];   // cr, cg
                const ulonglong2 r4 = rec2[j][4];   // cb, cb
                const u64 dx2 = fadd2(px2, r0.x);
                const u64 t0  = fmul2(r1.x, dx2);
                const u64 u2  = ffma2(t0, dx2, r2.y);
                const u64 kx2 = fmul2(r1.y, dx2);
                const u64 dyA = fadd2(pyA, r0.y);
                const u64 qA  = ffma2(r2.x, dyA, kx2);
                const u64 pwA = ffma2(dyA, qA, u2);
                const u64 dyB = fadd2(pyB, r0.y);
                const u64 qB  = ffma2(r2.x, dyB, kx2);
                const u64 pwB = ffma2(dyB, qB, u2);
                F2U PA, PB; PA.u = pwA; PB.u = pwB;
                F2U alA, alB;
                alA.f.x = clampa(ex2f(PA.f.x));
                alA.f.y = clampa(ex2f(PA.f.y));
                alB.f.x = clampa(ex2f(PB.f.x));
                alB.f.y = clampa(ex2f(PB.f.y));
                const u64 wvA = fmul2(alA.u, trA);
                trA = ffma2(alA.u, m1, trA);
                const u64 wvB = fmul2(alB.u, trB);
                trB = ffma2(alB.u, m1, trB);
                aR0 = ffma2(wvA, r3.x, aR0);
                aG0 = ffma2(wvA, r3.y, aG0);
                aB0 = ffma2(wvA, r4.x, aB0);
                aR1 = ffma2(wvB, r3.x, aR1);
                aG1 = ffma2(wvB, r3.y, aG1);
                aB1 = ffma2(wvB, r4.x, aB1);
            }
            last = j + 1;
        }
    }
    GAP(last, KG)
    #undef GAP

    // ---- epilogue: write 4 pixels ----
    const int gx = tx * 64 + lx;
    const int gy = ty * 64 + qtr * 16 + bl * 4;
    F2U R0, G0, B0, R1, G1, B1;
    R0.u = aR0; G0.u = aG0; B0.u = aB0;
    R1.u = aR1; G1.u = aG1; B1.u = aB1;
    float* o = out + ((size_t)gy * WIMG + gx) * 3;
    o[0] = R0.f.x; o[1] = G0.f.x; o[2] = B0.f.x;  o += WIMG * 3;
    o[0] = R0.f.y; o[1] = G0.f.y; o[2] = B0.f.y;  o += WIMG * 3;
    o[0] = R1.f.x; o[1] = G1.f.x; o[2] = B1.f.x;  o += WIMG * 3;
    o[0] = R1.f.y; o[1] = G1.f.y; o[2] = B1.f.y;
}

extern "C" void kernel_launch(void* const* d_in, const int* in_sizes, int n_in,
                              void* d_out, int out_size)
{
    const float* mu   = (const float*)d_in[0];
    const float* cov  = (const float*)d_in[1];
    const float* opac = (const float*)d_in[2];
    const float* col  = (const float*)d_in[3];
    const int*   tidx = (const int*)  d_in[4];
    float* out = (float*)d_out;

    // 64 tiles x 4 quarters = 256 CTAs, 256 threads, single launch
    fused_kernel<<<256, 256>>>(mu, cov, opac, col, tidx, out);
}